// round 3
// baseline (speedup 1.0000x reference)
#include <cuda_runtime.h>
#include <math.h>

#define BB 16
#define SS 1024
#define DD 1024
#define HH 16
#define DH 64

// Device scratch (no allocations allowed).
__device__ float g_q[BB * HH * SS * DH];          // 64 MB, pre-scaled by 0.125, tf32-rounded
__device__ float g_k[BB * HH * SS * DH];          // tf32-rounded
__device__ float g_v[BB * HH * SS * DH];          // tf32-rounded
__device__ float g_x[BB * SS * DD];               // tf32-rounded copy of X
__device__ float g_w[3 * DD * DD];                // tf32-rounded copies of Wq,Wk,Wv

// ---------------------------------------------------------------------------
__device__ __forceinline__ float to_tf32(float x) {
    float r;
    asm("cvt.rna.tf32.f32 %0, %1;" : "=f"(r) : "f"(x));
    return r;
}

__device__ __forceinline__ void mma_tf32(float* d, const unsigned* a, const unsigned* b) {
    asm volatile(
        "mma.sync.aligned.m16n8k8.row.col.f32.tf32.tf32.f32 "
        "{%0,%1,%2,%3},{%4,%5,%6,%7},{%8,%9},{%0,%1,%2,%3};"
        : "+f"(d[0]), "+f"(d[1]), "+f"(d[2]), "+f"(d[3])
        : "r"(a[0]), "r"(a[1]), "r"(a[2]), "r"(a[3]), "r"(b[0]), "r"(b[1]));
}

__device__ __forceinline__ unsigned smem_u32(const void* p) {
    return (unsigned)__cvta_generic_to_shared(p);
}

__device__ __forceinline__ void cp16(unsigned dst, const void* src) {
    asm volatile("cp.async.cg.shared.global [%0], [%1], 16;" :: "r"(dst), "l"(src));
}
__device__ __forceinline__ void cp_commit() {
    asm volatile("cp.async.commit_group;");
}
template <int N>
__device__ __forceinline__ void cp_wait() {
    asm volatile("cp.async.wait_group %0;" :: "n"(N));
}

// ---------------------------------------------------------------------------
// Pre-pass: tf32-round a buffer (float4 grid-stride).
// ---------------------------------------------------------------------------
__global__ void round_copy(float* __restrict__ dst, const float* __restrict__ src, int n4)
{
    int i = blockIdx.x * blockDim.x + threadIdx.x;
    if (i < n4) {
        float4 v = ((const float4*)src)[i];
        v.x = to_tf32(v.x); v.y = to_tf32(v.y); v.z = to_tf32(v.z); v.w = to_tf32(v.w);
        ((float4*)dst)[i] = v;
    }
}

// ---------------------------------------------------------------------------
// Fused QKV GEMM: Y = (X @ W^T + b) * scale, tf32-rounded, head-split store.
// grid (24, 128): blockIdx.x -> {wsel = x>>3, n0 = (x&7)*128}. BM=BN=128,
// BK=32, 256 threads (8 warps, 4x2), warp tile 32x64, cp.async double buffer.
// ---------------------------------------------------------------------------
__global__ __launch_bounds__(256)
void qkv_gemm(const float* __restrict__ bq, const float* __restrict__ bk,
              const float* __restrict__ bv)
{
    extern __shared__ float sm[];
    float* sbuf[2][2];   // [buf][A/B]
    sbuf[0][0] = sm;              sbuf[0][1] = sm + 4608;
    sbuf[1][0] = sm + 9216;       sbuf[1][1] = sm + 13824;

    const int tid  = threadIdx.x;
    const int lane = tid & 31;
    const int warp = tid >> 5;
    const int bx   = blockIdx.x;
    const int wsel = bx >> 3;
    const int n0   = (bx & 7) * 128;
    const int m0   = blockIdx.y * 128;

    const float* __restrict__ Wm  = g_w + (size_t)wsel * DD * DD;
    const float* __restrict__ bias = (wsel == 0) ? bq : (wsel == 1) ? bk : bv;
    float* __restrict__ Y = (wsel == 0) ? g_q : (wsel == 1) ? g_k : g_v;
    const float scale = (wsel == 0) ? 0.125f : 1.0f;

    const int wm = (warp & 3) * 32;
    const int wn = (warp >> 2) * 64;
    const int r4 = lane >> 2;
    const int c4 = lane & 3;

    // cp.async mapping: row = tid>>1 (0..127), col base = (tid&1)*16, 4 x 16B
    const int prow = tid >> 1;
    const int pcb  = (tid & 1) * 16;
    const float* srcA = g_x + (size_t)(m0 + prow) * DD + pcb;
    const float* srcB = Wm  + (size_t)(n0 + prow) * DD + pcb;

    float acc[2][8][4];
    #pragma unroll
    for (int i = 0; i < 2; i++)
        #pragma unroll
        for (int j = 0; j < 8; j++)
            #pragma unroll
            for (int c = 0; c < 4; c++) acc[i][j][c] = 0.0f;

    // prefetch k-tile 0
    {
        unsigned dA = smem_u32(sbuf[0][0] + prow * 36 + pcb);
        unsigned dB = smem_u32(sbuf[0][1] + prow * 36 + pcb);
        #pragma unroll
        for (int i = 0; i < 4; i++) {
            cp16(dA + i * 16, srcA + i * 4);
            cp16(dB + i * 16, srcB + i * 4);
        }
        cp_commit();
    }

    for (int kt = 0; kt < 32; kt++) {
        const int cur = kt & 1;
        if (kt < 31) {
            const int k0n = (kt + 1) * 32;
            unsigned dA = smem_u32(sbuf[cur ^ 1][0] + prow * 36 + pcb);
            unsigned dB = smem_u32(sbuf[cur ^ 1][1] + prow * 36 + pcb);
            #pragma unroll
            for (int i = 0; i < 4; i++) {
                cp16(dA + i * 16, srcA + k0n + i * 4);
                cp16(dB + i * 16, srcB + k0n + i * 4);
            }
            cp_commit();
            cp_wait<1>();
        } else {
            cp_wait<0>();
        }
        __syncthreads();

        const float* cA = sbuf[cur][0];
        const float* cB = sbuf[cur][1];
        #pragma unroll
        for (int ks = 0; ks < 4; ks++) {
            const int kk = ks * 8;
            unsigned af[2][4];
            #pragma unroll
            for (int mt = 0; mt < 2; mt++) {
                const int rb = wm + mt * 16;
                af[mt][0] = __float_as_uint(cA[(rb + r4    ) * 36 + kk + c4    ]);
                af[mt][1] = __float_as_uint(cA[(rb + r4 + 8) * 36 + kk + c4    ]);
                af[mt][2] = __float_as_uint(cA[(rb + r4    ) * 36 + kk + c4 + 4]);
                af[mt][3] = __float_as_uint(cA[(rb + r4 + 8) * 36 + kk + c4 + 4]);
            }
            #pragma unroll
            for (int nt = 0; nt < 8; nt++) {
                const int cb = wn + nt * 8;
                unsigned bf[2];
                bf[0] = __float_as_uint(cB[(cb + r4) * 36 + kk + c4    ]);
                bf[1] = __float_as_uint(cB[(cb + r4) * 36 + kk + c4 + 4]);
                mma_tf32(acc[0][nt], af[0], bf);
                mma_tf32(acc[1][nt], af[1], bf);
            }
        }
        __syncthreads();
    }

    // Epilogue: (acc + bias) * scale, tf32-rounded, head-split scatter.
    #pragma unroll
    for (int mt = 0; mt < 2; mt++) {
        const int mA = m0 + wm + mt * 16 + r4;
        const int mB = mA + 8;
        const int bA = mA >> 10, sA_ = mA & 1023;
        const int bB = mB >> 10, sB_ = mB & 1023;
        #pragma unroll
        for (int nt = 0; nt < 8; nt++) {
            const int col = n0 + wn + nt * 8 + 2 * c4;
            const int h = col >> 6, d = col & 63;
            const float b0 = bias[col], b1 = bias[col + 1];
            float2 vA = make_float2(to_tf32((acc[mt][nt][0] + b0) * scale),
                                    to_tf32((acc[mt][nt][1] + b1) * scale));
            float2 vB = make_float2(to_tf32((acc[mt][nt][2] + b0) * scale),
                                    to_tf32((acc[mt][nt][3] + b1) * scale));
            *(float2*)(Y + (((size_t)(bA * HH + h) * SS + sA_) * DH) + d) = vA;
            *(float2*)(Y + (((size_t)(bB * HH + h) * SS + sB_) * DH) + d) = vB;
        }
    }
}

// ---------------------------------------------------------------------------
// Flash attention, tf32 mma. Block = 128 thr (4 warps), 32 q-rows per warp
// (2 m16 tiles), BC=32, Dh=64. Q fragments live in registers for the whole
// loop; K/V tiles double-buffered via cp.async; P through per-warp smem.
// Dynamic smem: K[2][32][68], V[2][32][72], P[4][32][36]  (54272 B)
// ---------------------------------------------------------------------------
#define SK_OFF 0
#define SV_OFF (2 * 32 * 68)
#define SP_OFF (SV_OFF + 2 * 32 * 72)
#define ATTN_SMEM ((SP_OFF + 4 * 32 * 36) * 4)

__global__ __launch_bounds__(128)
void attn_kernel(float* __restrict__ out)
{
    extern __shared__ float sm[];
    float* sK[2] = { sm + SK_OFF, sm + SK_OFF + 32 * 68 };
    float* sV[2] = { sm + SV_OFF, sm + SV_OFF + 32 * 72 };

    const int tid  = threadIdx.x;
    const int lane = tid & 31;
    const int warp = tid >> 5;
    const int bh   = blockIdx.y;
    const int b    = bh >> 4;
    const int h    = bh & 15;
    const int qrow0 = blockIdx.x * 128 + warp * 32;

    const int r4 = lane >> 2;
    const int c4 = lane & 3;

    float* sPw = sm + SP_OFF + warp * (32 * 36);

    const float* __restrict__ Qb = g_q + (size_t)bh * SS * DH;
    const float* __restrict__ Kb = g_k + (size_t)bh * SS * DH;
    const float* __restrict__ Vb = g_v + (size_t)bh * SS * DH;

    // Q fragments (pre-scaled, pre-rounded in gmem) -> registers, kept all loop.
    unsigned qa[2][8][4];
    #pragma unroll
    for (int mt = 0; mt < 2; mt++) {
        const int rA = qrow0 + mt * 16 + r4;
        #pragma unroll
        for (int kt = 0; kt < 8; kt++) {
            const int cc = kt * 8 + c4;
            qa[mt][kt][0] = __float_as_uint(Qb[(size_t)rA * DH + cc]);
            qa[mt][kt][1] = __float_as_uint(Qb[(size_t)(rA + 8) * DH + cc]);
            qa[mt][kt][2] = __float_as_uint(Qb[(size_t)rA * DH + cc + 4]);
            qa[mt][kt][3] = __float_as_uint(Qb[(size_t)(rA + 8) * DH + cc + 4]);
        }
    }

    float o[2][8][4];
    #pragma unroll
    for (int mt = 0; mt < 2; mt++)
        #pragma unroll
        for (int nt = 0; nt < 8; nt++)
            #pragma unroll
            for (int c = 0; c < 4; c++) o[mt][nt][c] = 0.0f;
    float mv[2][2] = { {-INFINITY, -INFINITY}, {-INFINITY, -INFINITY} };
    float lv[2][2] = { {0.0f, 0.0f}, {0.0f, 0.0f} };

    // cp.async mapping for a 32x64 tile: row = tid>>2, colbase = (tid&3)*16
    const int prow = tid >> 2;
    const int pcb  = (tid & 3) * 16;

    // prefetch tile 0
    {
        const float* ks = Kb + (size_t)prow * DH + pcb;
        const float* vs = Vb + (size_t)prow * DH + pcb;
        unsigned dK = smem_u32(sK[0] + prow * 68 + pcb);
        unsigned dV = smem_u32(sV[0] + prow * 72 + pcb);
        #pragma unroll
        for (int i = 0; i < 4; i++) {
            cp16(dK + i * 16, ks + i * 4);
            cp16(dV + i * 16, vs + i * 4);
        }
        cp_commit();
    }

    for (int t = 0; t < 32; t++) {
        const int cur = t & 1;
        if (t < 31) {
            const size_t roff = (size_t)((t + 1) * 32 + prow) * DH + pcb;
            const float* ks = Kb + roff;
            const float* vs = Vb + roff;
            unsigned dK = smem_u32(sK[cur ^ 1] + prow * 68 + pcb);
            unsigned dV = smem_u32(sV[cur ^ 1] + prow * 72 + pcb);
            #pragma unroll
            for (int i = 0; i < 4; i++) {
                cp16(dK + i * 16, ks + i * 4);
                cp16(dV + i * 16, vs + i * 4);
            }
            cp_commit();
            cp_wait<1>();
        } else {
            cp_wait<0>();
        }
        __syncthreads();

        const float* cK = sK[cur];
        const float* cV = sV[cur];

        // S = Q @ K^T : [2 m-tiles][4 kv n-tiles], B-frags shared across m-tiles
        float s[2][4][4];
        #pragma unroll
        for (int mt = 0; mt < 2; mt++)
            #pragma unroll
            for (int nt = 0; nt < 4; nt++)
                #pragma unroll
                for (int c = 0; c < 4; c++) s[mt][nt][c] = 0.0f;
        #pragma unroll
        for (int kt = 0; kt < 8; kt++) {
            #pragma unroll
            for (int nt = 0; nt < 4; nt++) {
                unsigned bf[2];
                bf[0] = __float_as_uint(cK[(nt * 8 + r4) * 68 + kt * 8 + c4    ]);
                bf[1] = __float_as_uint(cK[(nt * 8 + r4) * 68 + kt * 8 + c4 + 4]);
                mma_tf32(s[0][nt], qa[0][kt], bf);
                mma_tf32(s[1][nt], qa[1][kt], bf);
            }
        }

        // online softmax per m-tile
        #pragma unroll
        for (int mt = 0; mt < 2; mt++) {
            float tm0 = -INFINITY, tm1 = -INFINITY;
            #pragma unroll
            for (int nt = 0; nt < 4; nt++) {
                tm0 = fmaxf(tm0, fmaxf(s[mt][nt][0], s[mt][nt][1]));
                tm1 = fmaxf(tm1, fmaxf(s[mt][nt][2], s[mt][nt][3]));
            }
            tm0 = fmaxf(tm0, __shfl_xor_sync(0xffffffffu, tm0, 1));
            tm0 = fmaxf(tm0, __shfl_xor_sync(0xffffffffu, tm0, 2));
            tm1 = fmaxf(tm1, __shfl_xor_sync(0xffffffffu, tm1, 1));
            tm1 = fmaxf(tm1, __shfl_xor_sync(0xffffffffu, tm1, 2));

            const float mn0 = fmaxf(mv[mt][0], tm0);
            const float mn1 = fmaxf(mv[mt][1], tm1);
            const float sc0 = __expf(mv[mt][0] - mn0);
            const float sc1 = __expf(mv[mt][1] - mn1);
            mv[mt][0] = mn0; mv[mt][1] = mn1;

            float ps0 = 0.0f, ps1 = 0.0f;
            #pragma unroll
            for (int nt = 0; nt < 4; nt++) {
                s[mt][nt][0] = __expf(s[mt][nt][0] - mn0);
                s[mt][nt][1] = __expf(s[mt][nt][1] - mn0);
                s[mt][nt][2] = __expf(s[mt][nt][2] - mn1);
                s[mt][nt][3] = __expf(s[mt][nt][3] - mn1);
                ps0 += s[mt][nt][0] + s[mt][nt][1];
                ps1 += s[mt][nt][2] + s[mt][nt][3];
            }
            ps0 += __shfl_xor_sync(0xffffffffu, ps0, 1);
            ps0 += __shfl_xor_sync(0xffffffffu, ps0, 2);
            ps1 += __shfl_xor_sync(0xffffffffu, ps1, 1);
            ps1 += __shfl_xor_sync(0xffffffffu, ps1, 2);
            lv[mt][0] = lv[mt][0] * sc0 + ps0;
            lv[mt][1] = lv[mt][1] * sc1 + ps1;

            #pragma unroll
            for (int nt = 0; nt < 8; nt++) {
                o[mt][nt][0] *= sc0; o[mt][nt][1] *= sc0;
                o[mt][nt][2] *= sc1; o[mt][nt][3] *= sc1;
            }

            // store P (tf32-rounded) to warp-private smem
            #pragma unroll
            for (int nt = 0; nt < 4; nt++) {
                float2 pA = make_float2(to_tf32(s[mt][nt][0]), to_tf32(s[mt][nt][1]));
                float2 pB = make_float2(to_tf32(s[mt][nt][2]), to_tf32(s[mt][nt][3]));
                *(float2*)&sPw[(mt * 16 + r4    ) * 36 + nt * 8 + 2 * c4] = pA;
                *(float2*)&sPw[(mt * 16 + r4 + 8) * 36 + nt * 8 + 2 * c4] = pB;
            }
        }
        __syncwarp();

        // P A-fragments
        unsigned pa[2][4][4];
        #pragma unroll
        for (int mt = 0; mt < 2; mt++)
            #pragma unroll
            for (int kt = 0; kt < 4; kt++) {
                pa[mt][kt][0] = __float_as_uint(sPw[(mt * 16 + r4    ) * 36 + kt * 8 + c4    ]);
                pa[mt][kt][1] = __float_as_uint(sPw[(mt * 16 + r4 + 8) * 36 + kt * 8 + c4    ]);
                pa[mt][kt][2] = __float_as_uint(sPw[(mt * 16 + r4    ) * 36 + kt * 8 + c4 + 4]);
                pa[mt][kt][3] = __float_as_uint(sPw[(mt * 16 + r4 + 8) * 36 + kt * 8 + c4 + 4]);
            }

        // O += P @ V  (B-frags shared across m-tiles)
        #pragma unroll
        for (int nt = 0; nt < 8; nt++) {
            #pragma unroll
            for (int kt = 0; kt < 4; kt++) {
                unsigned bf[2];
                bf[0] = __float_as_uint(cV[(kt * 8 + c4    ) * 72 + nt * 8 + r4]);
                bf[1] = __float_as_uint(cV[(kt * 8 + c4 + 4) * 72 + nt * 8 + r4]);
                mma_tf32(o[0][nt], pa[0][kt], bf);
                mma_tf32(o[1][nt], pa[1][kt], bf);
            }
        }
        __syncthreads();
    }

    // epilogue
    #pragma unroll
    for (int mt = 0; mt < 2; mt++) {
        const float inv0 = 1.0f / lv[mt][0];
        const float inv1 = 1.0f / lv[mt][1];
        const int rA = qrow0 + mt * 16 + r4;
        const int rB = rA + 8;
        float* oA = out + ((size_t)(b * SS + rA)) * DD + h * DH;
        float* oB = out + ((size_t)(b * SS + rB)) * DD + h * DH;
        #pragma unroll
        for (int nt = 0; nt < 8; nt++) {
            const int d = nt * 8 + 2 * c4;
            *(float2*)(oA + d) = make_float2(o[mt][nt][0] * inv0, o[mt][nt][1] * inv0);
            *(float2*)(oB + d) = make_float2(o[mt][nt][2] * inv1, o[mt][nt][3] * inv1);
        }
    }
}

// ---------------------------------------------------------------------------
extern "C" void kernel_launch(void* const* d_in, const int* in_sizes, int n_in,
                              void* d_out, int out_size)
{
    const float* x  = (const float*)d_in[0];
    const float* Wq = (const float*)d_in[1];
    const float* bq = (const float*)d_in[2];
    const float* Wk = (const float*)d_in[3];
    const float* bk = (const float*)d_in[4];
    const float* Wv = (const float*)d_in[5];
    const float* bv = (const float*)d_in[6];
    float* out = (float*)d_out;

    // opt-in large dynamic smem (idempotent; ignore errors during capture)
    cudaFuncSetAttribute(qkv_gemm, cudaFuncAttributeMaxDynamicSharedMemorySize, 18432 * 4);
    cudaFuncSetAttribute(attn_kernel, cudaFuncAttributeMaxDynamicSharedMemorySize, ATTN_SMEM);

    float* gx; cudaGetSymbolAddress((void**)&gx, g_x);
    float* gw; cudaGetSymbolAddress((void**)&gw, g_w);

    // pre-pass: tf32-round X and the three weight matrices
    round_copy<<<(BB * SS * DD / 4 + 255) / 256, 256>>>(gx, x, BB * SS * DD / 4);
    round_copy<<<(DD * DD / 4 + 255) / 256, 256>>>(gw,               Wq, DD * DD / 4);
    round_copy<<<(DD * DD / 4 + 255) / 256, 256>>>(gw + DD * DD,     Wk, DD * DD / 4);
    round_copy<<<(DD * DD / 4 + 255) / 256, 256>>>(gw + 2 * DD * DD, Wv, DD * DD / 4);

    dim3 gg(24, 128);
    qkv_gemm<<<gg, 256, 18432 * 4>>>(bq, bk, bv);

    dim3 ga(SS / 128, BB * HH);   // (8, 256)
    attn_kernel<<<ga, 128, ATTN_SMEM>>>(out);
}